// round 6
// baseline (speedup 1.0000x reference)
#include <cuda_runtime.h>
#include <cstdint>

#define BS   8
#define SEQ  1024
#define DIM  1024
#define NH   16
#define HD   64
#define NNB  50

typedef unsigned long long ull;
struct __align__(16) u64x2 { ull a, b; };

__device__ __forceinline__ ull fma2(ull a, ull b, ull c) {
    ull d;
    asm("fma.rn.f32x2 %0, %1, %2, %3;" : "=l"(d) : "l"(a), "l"(b), "l"(c));
    return d;
}
__device__ __forceinline__ ull pack2(float x, float y) {
    ull d;
    asm("mov.b64 %0, {%1, %2};" : "=l"(d) : "f"(x), "f"(y));
    return d;
}
__device__ __forceinline__ float lo32(ull v) { return __uint_as_float((unsigned)(v & 0xffffffffu)); }
__device__ __forceinline__ float hi32(ull v) { return __uint_as_float((unsigned)(v >> 32)); }

__device__ __forceinline__ void cpa16(uint32_t dst, const void* src) {
    asm volatile("cp.async.ca.shared.global [%0], [%1], 16;" :: "r"(dst), "l"(src) : "memory");
}
#define CP_COMMIT()  asm volatile("cp.async.commit_group;" ::: "memory")
#define CP_WAIT(n)   asm volatile("cp.async.wait_group %0;" :: "n"(n) : "memory")

// ---------------- scratch (static device globals; no allocation) ----------------
__device__ __align__(16) float g_xn [BS*DIM];           // pooled neighbors
__device__ __align__(16) float g_q  [BS*DIM];           // query projection (already /8)
__device__ __align__(16) float g_ws [BS*NH*DIM];        // per-head score weight vectors
__device__ __align__(16) float g_scp[16][BS*NH*SEQ];    // partial scores (k-split 16)
__device__ __align__(16) float g_w  [BS*NH*SEQ];        // softmax weights
__device__ __align__(16) float g_xwp[16][BS*NH*DIM];    // partial weighted pools (s-split 16)
__device__ __align__(16) float g_xw [BS*NH*DIM];        // weighted pooled x per head
__device__ __align__(16) float g_ctx[BS*DIM];           // context vector per batch
__device__ __align__(16) float g_out[BS*DIM];           // attention output per batch

// ---------------- K1: masked mean-pool of neighbors. grid (4 dim-chunks, BS), 64 thr ----------------
__global__ __launch_bounds__(64) void k_pool(const float* __restrict__ xnb,
                                             const float* __restrict__ nm) {
    int b = blockIdx.y;
    int c = blockIdx.x;
    __shared__ float snm[NNB];
    if (threadIdx.x < NNB) snm[threadIdx.x] = nm[b*NNB + threadIdx.x];
    __syncthreads();
    float den = 0.f;
    #pragma unroll
    for (int n = 0; n < NNB; n++) den += snm[n];
    float inv = 1.f / den;
    int i = c*256 + threadIdx.x*4;
    float4 a = make_float4(0.f, 0.f, 0.f, 0.f);
    #pragma unroll 5
    for (int n = 0; n < NNB; n++) {
        float4 v = *(const float4*)&xnb[(b*NNB + n)*DIM + i];
        float w = snm[n];
        a.x += v.x*w; a.y += v.y*w; a.z += v.z*w; a.w += v.w*w;
    }
    a.x *= inv; a.y *= inv; a.z *= inv; a.w *= inv;
    *(float4*)&g_xn[b*DIM + i] = a;
}

// ---------------- K2: q[b,j] = (qw[j,:]·xn[b,:] + qb[j]) / 8 ----------------
__global__ __launch_bounds__(256) void k_q(const float* __restrict__ qw,
                                           const float* __restrict__ qb) {
    int j = blockIdx.x;
    float p[BS];
    #pragma unroll
    for (int b = 0; b < BS; b++) p[b] = 0.f;
    #pragma unroll
    for (int it = 0; it < 4; it++) {
        int i = threadIdx.x + it*256;
        float wv = qw[j*DIM + i];
        #pragma unroll
        for (int b = 0; b < BS; b++) p[b] += wv * g_xn[b*DIM + i];
    }
    #pragma unroll
    for (int off = 16; off; off >>= 1)
        #pragma unroll
        for (int b = 0; b < BS; b++) p[b] += __shfl_down_sync(0xffffffffu, p[b], off);
    __shared__ float red[8][BS];
    int w = threadIdx.x >> 5, lane = threadIdx.x & 31;
    if (lane == 0) {
        #pragma unroll
        for (int b = 0; b < BS; b++) red[w][b] = p[b];
    }
    __syncthreads();
    if (threadIdx.x < BS) {
        int b = threadIdx.x;
        float s = 0.f;
        #pragma unroll
        for (int w2 = 0; w2 < 8; w2++) s += red[w2][b];
        g_q[b*DIM + j] = (s + qb[j]) * 0.125f;
    }
}

// ---------------- K3: ws[b,h,i] = sum_{jj<64} q[b,h*64+jj] * kw[h*64+jj, i] ----------------
__global__ __launch_bounds__(128) void k_ws(const float* __restrict__ kw) {
    int ic = blockIdx.x;
    int h  = blockIdx.y;
    int i  = ic*128 + threadIdx.x;
    __shared__ float qs[BS][HD];
    for (int e = threadIdx.x; e < BS*HD; e += 128) {
        int b = e >> 6, jj = e & 63;
        qs[b][jj] = g_q[b*DIM + h*HD + jj];
    }
    __syncthreads();
    float acc[BS];
    #pragma unroll
    for (int b = 0; b < BS; b++) acc[b] = 0.f;
    #pragma unroll 4
    for (int jj = 0; jj < HD; jj++) {
        float kwv = kw[(h*HD + jj)*DIM + i];
        #pragma unroll
        for (int b = 0; b < BS; b++) acc[b] += qs[b][jj] * kwv;
    }
    #pragma unroll
    for (int b = 0; b < BS; b++) g_ws[(b*NH + h)*DIM + i] = acc[b];
}

// ---------------- K4: partial scores. grid (16 ksplit, 4 stile, 8 b), 256 thr ----------------
// Thread owns one seq row; accumulates all 16 heads as 8 packed f32x2.
// x staged via cp.async double buffer (s-major, 16k per chunk, 4 chunks of k-range 64).
__global__ __launch_bounds__(256) void k_scores(const float* __restrict__ x) {
    int ks = blockIdx.x;           // k range [ks*64, ks*64+64)
    int st = blockIdx.y;           // 256 seq rows
    int b  = blockIdx.z;
    int s0 = st*256, k0 = ks*64;
    __shared__ __align__(16) float xs [2][256*20];   // [buf][s][16 k + pad4]
    __shared__ __align__(16) float wss[2][16*20];    // [buf][kk][16 h + pad4]
    int tid = threadIdx.x;
    int s = s0 + tid;
    const float* xrow = &x[(b*SEQ + s)*DIM + k0];
    uint32_t xs_base = (uint32_t)__cvta_generic_to_shared(&xs[0][0]);
    int wkk = tid & 15, wh = tid >> 4;
    const float* wsrc = &g_ws[(b*NH + wh)*DIM + k0 + wkk];

    ull acc[8];
    #pragma unroll
    for (int p = 0; p < 8; p++) acc[p] = 0ull;

#define SC_ISSUE(c) { \
    uint32_t d = xs_base + (uint32_t)(((c)&1)*256*20 + tid*20)*4u; \
    const float* sp = xrow + (c)*16; \
    cpa16(d,      sp);     cpa16(d + 16, sp + 4); \
    cpa16(d + 32, sp + 8); cpa16(d + 48, sp + 12); \
    wss[(c)&1][wkk*20 + wh] = wsrc[(c)*16]; \
    CP_COMMIT(); }

#define SC_COMPUTE(c, WN) { \
    CP_WAIT(WN); \
    __syncthreads(); \
    const float* xp = &xs[(c)&1][tid*20]; \
    const float* wp = &wss[(c)&1][0]; \
    float4 xv[4]; \
    xv[0] = ((const float4*)xp)[0]; xv[1] = ((const float4*)xp)[1]; \
    xv[2] = ((const float4*)xp)[2]; xv[3] = ((const float4*)xp)[3]; \
    _Pragma("unroll") \
    for (int g = 0; g < 4; g++) { \
        _Pragma("unroll") \
        for (int e = 0; e < 4; e++) { \
            float xe = (&xv[g].x)[e]; \
            ull xd = pack2(xe, xe); \
            int kk = g*4 + e; \
            u64x2 w0 = *(const u64x2*)&wp[kk*20 + 0]; \
            u64x2 w1 = *(const u64x2*)&wp[kk*20 + 4]; \
            u64x2 w2 = *(const u64x2*)&wp[kk*20 + 8]; \
            u64x2 w3 = *(const u64x2*)&wp[kk*20 + 12]; \
            acc[0] = fma2(w0.a, xd, acc[0]); acc[1] = fma2(w0.b, xd, acc[1]); \
            acc[2] = fma2(w1.a, xd, acc[2]); acc[3] = fma2(w1.b, xd, acc[3]); \
            acc[4] = fma2(w2.a, xd, acc[4]); acc[5] = fma2(w2.b, xd, acc[5]); \
            acc[6] = fma2(w3.a, xd, acc[6]); acc[7] = fma2(w3.b, xd, acc[7]); \
        } \
    } }

    SC_ISSUE(0); SC_ISSUE(1);
    SC_COMPUTE(0, 1); __syncthreads(); SC_ISSUE(2);
    SC_COMPUTE(1, 1); __syncthreads(); SC_ISSUE(3);
    SC_COMPUTE(2, 1);
    SC_COMPUTE(3, 0);

    float* dst = g_scp[ks];
    int rbase = (b*NH)*SEQ + s;
    #pragma unroll
    for (int p = 0; p < 8; p++) {
        dst[rbase + (2*p  )*SEQ] = lo32(acc[p]);
        dst[rbase + (2*p+1)*SEQ] = hi32(acc[p]);
    }
#undef SC_ISSUE
#undef SC_COMPUTE
}

// ---------------- K5: softmax over seq per (b,h); sums the 16 k-split partials ----------------
__global__ __launch_bounds__(256) void k_softmax(const int* __restrict__ mask) {
    int h = blockIdx.x, b = blockIdx.y;
    int base = (b*NH + h)*SEQ;
    int tid = threadIdx.x;
    float v[4];
    float m = -3.4e38f;
    #pragma unroll
    for (int t = 0; t < 4; t++) {
        int s = tid + t*256;
        float sc = 0.f;
        #pragma unroll
        for (int ks = 0; ks < 16; ks++) sc += g_scp[ks][base + s];
        if (mask[b*SEQ + s] == 0) sc = -1e30f;
        v[t] = sc;
        m = fmaxf(m, sc);
    }
    __shared__ float sred[8];
    int w = tid >> 5, lane = tid & 31;
    #pragma unroll
    for (int off = 16; off; off >>= 1) m = fmaxf(m, __shfl_xor_sync(0xffffffffu, m, off));
    if (lane == 0) sred[w] = m;
    __syncthreads();
    float m0 = sred[0];
    #pragma unroll
    for (int w2 = 1; w2 < 8; w2++) m0 = fmaxf(m0, sred[w2]);
    __syncthreads();
    float sum = 0.f;
    #pragma unroll
    for (int t = 0; t < 4; t++) { v[t] = expf(v[t] - m0); sum += v[t]; }
    #pragma unroll
    for (int off = 16; off; off >>= 1) sum += __shfl_xor_sync(0xffffffffu, sum, off);
    if (lane == 0) sred[w] = sum;
    __syncthreads();
    float tot = 0.f;
    #pragma unroll
    for (int w2 = 0; w2 < 8; w2++) tot += sred[w2];
    float inv = 1.f / tot;
    #pragma unroll
    for (int t = 0; t < 4; t++) g_w[base + tid + t*256] = v[t] * inv;
}

// ---------------- K6: partial weighted pools. grid (16 schunk, 4 ichunk, 8 b), f32x2 ----------------
__global__ __launch_bounds__(256) void k_xw(const float* __restrict__ x) {
    int sc = blockIdx.x;   // seq chunk (64)
    int ic = blockIdx.y;   // dim chunk (256)
    int b  = blockIdx.z;
    int i  = ic*256 + threadIdx.x;
    __shared__ __align__(16) float wt[64*20];   // [s][16 h + pad4]
    for (int e = threadIdx.x; e < 1024; e += 256) {
        int s = e & 63, h = e >> 6;
        wt[s*20 + h] = g_w[(b*NH + h)*SEQ + sc*64 + s];
    }
    __syncthreads();
    ull acc[8];
    #pragma unroll
    for (int p = 0; p < 8; p++) acc[p] = 0ull;
    const float* xp = &x[(b*SEQ + sc*64)*DIM + i];
    #pragma unroll 8
    for (int ss = 0; ss < 64; ss++) {
        float xv = xp[ss*DIM];
        ull xd = pack2(xv, xv);
        const float* wr = &wt[ss*20];
        u64x2 w0 = *(const u64x2*)&wr[0];
        u64x2 w1 = *(const u64x2*)&wr[4];
        u64x2 w2 = *(const u64x2*)&wr[8];
        u64x2 w3 = *(const u64x2*)&wr[12];
        acc[0] = fma2(w0.a, xd, acc[0]); acc[1] = fma2(w0.b, xd, acc[1]);
        acc[2] = fma2(w1.a, xd, acc[2]); acc[3] = fma2(w1.b, xd, acc[3]);
        acc[4] = fma2(w2.a, xd, acc[4]); acc[5] = fma2(w2.b, xd, acc[5]);
        acc[6] = fma2(w3.a, xd, acc[6]); acc[7] = fma2(w3.b, xd, acc[7]);
    }
    float* dst = g_xwp[sc];
    #pragma unroll
    for (int p = 0; p < 8; p++) {
        dst[(b*NH + 2*p  )*DIM + i] = lo32(acc[p]);
        dst[(b*NH + 2*p+1)*DIM + i] = hi32(acc[p]);
    }
}

// ---------------- K6b: reduce the 16 seq-chunk partials ----------------
__global__ __launch_bounds__(256) void k_xwred() {
    int idx = blockIdx.x*256 + threadIdx.x;   // 512 blocks -> 131072
    float s = 0.f;
    #pragma unroll
    for (int sc = 0; sc < 16; sc++) s += g_xwp[sc][idx];
    g_xw[idx] = s;
}

// ---------------- K7a: context[b,j] = vw[j,:]·xw[b, j/64, :] + vb[j] ----------------
__global__ __launch_bounds__(256) void k_ctx(const float* __restrict__ vw,
                                             const float* __restrict__ vb) {
    int j = blockIdx.x;
    int h = j >> 6;
    float p[BS];
    #pragma unroll
    for (int b = 0; b < BS; b++) p[b] = 0.f;
    #pragma unroll
    for (int it = 0; it < 4; it++) {
        int i = threadIdx.x + it*256;
        float wv = vw[j*DIM + i];
        #pragma unroll
        for (int b = 0; b < BS; b++) p[b] += wv * g_xw[(b*NH + h)*DIM + i];
    }
    #pragma unroll
    for (int off = 16; off; off >>= 1)
        #pragma unroll
        for (int b = 0; b < BS; b++) p[b] += __shfl_down_sync(0xffffffffu, p[b], off);
    __shared__ float red[8][BS];
    int w = threadIdx.x >> 5, lane = threadIdx.x & 31;
    if (lane == 0) {
        #pragma unroll
        for (int b = 0; b < BS; b++) red[w][b] = p[b];
    }
    __syncthreads();
    if (threadIdx.x < BS) {
        int b = threadIdx.x;
        float s = 0.f;
        #pragma unroll
        for (int w2 = 0; w2 < 8; w2++) s += red[w2][b];
        g_ctx[b*DIM + j] = s + vb[j];
    }
}

// ---------------- K7b: out[b,j] = ow[j,:]·ctx[b,:] + ob[j] ----------------
__global__ __launch_bounds__(256) void k_out(const float* __restrict__ ow,
                                             const float* __restrict__ ob) {
    int j = blockIdx.x;
    float p[BS];
    #pragma unroll
    for (int b = 0; b < BS; b++) p[b] = 0.f;
    #pragma unroll
    for (int it = 0; it < 4; it++) {
        int i = threadIdx.x + it*256;
        float wv = ow[j*DIM + i];
        #pragma unroll
        for (int b = 0; b < BS; b++) p[b] += wv * g_ctx[b*DIM + i];
    }
    #pragma unroll
    for (int off = 16; off; off >>= 1)
        #pragma unroll
        for (int b = 0; b < BS; b++) p[b] += __shfl_down_sync(0xffffffffu, p[b], off);
    __shared__ float red[8][BS];
    int w = threadIdx.x >> 5, lane = threadIdx.x & 31;
    if (lane == 0) {
        #pragma unroll
        for (int b = 0; b < BS; b++) red[w][b] = p[b];
    }
    __syncthreads();
    if (threadIdx.x < BS) {
        int b = threadIdx.x;
        float s = 0.f;
        #pragma unroll
        for (int w2 = 0; w2 < 8; w2++) s += red[w2][b];
        g_out[b*DIM + j] = s + ob[j];
    }
}

// ---------------- K8: y[b,s,:] = LN(x[b,s,:] + out[b,:]) * g + beta ----------------
__global__ __launch_bounds__(256) void k_ln(const float* __restrict__ x,
                                            const float* __restrict__ lg,
                                            const float* __restrict__ lb,
                                            float* __restrict__ y) {
    int row  = blockIdx.x*8 + (threadIdx.x >> 5);   // 8192 rows, warp per row
    int lane = threadIdx.x & 31;
    int b    = row >> 10;
    const float4* X4 = (const float4*)x;
    const float4* O4 = (const float4*)g_out;
    float4 hv[8];
    float sum = 0.f, sq = 0.f;
    #pragma unroll
    for (int j = 0; j < 8; j++) {
        float4 xv = X4[row*256 + lane + j*32];
        float4 ov = O4[b*256  + lane + j*32];
        float4 h;
        h.x = xv.x + ov.x; h.y = xv.y + ov.y; h.z = xv.z + ov.z; h.w = xv.w + ov.w;
        hv[j] = h;
        sum += h.x + h.y + h.z + h.w;
        sq  += h.x*h.x + h.y*h.y + h.z*h.z + h.w*h.w;
    }
    #pragma unroll
    for (int off = 16; off; off >>= 1) {
        sum += __shfl_xor_sync(0xffffffffu, sum, off);
        sq  += __shfl_xor_sync(0xffffffffu, sq,  off);
    }
    float mu  = sum * (1.f/1024.f);
    float var = sq  * (1.f/1024.f) - mu*mu;
    float rs  = rsqrtf(var + 1e-12f);
    const float4* G4 = (const float4*)lg;
    const float4* B4 = (const float4*)lb;
    float4* Y4 = (float4*)y;
    #pragma unroll
    for (int j = 0; j < 8; j++) {
        float4 gv = G4[lane + j*32];
        float4 bv = B4[lane + j*32];
        float4 o;
        o.x = (hv[j].x - mu)*rs*gv.x + bv.x;
        o.y = (hv[j].y - mu)*rs*gv.y + bv.y;
        o.z = (hv[j].z - mu)*rs*gv.z + bv.z;
        o.w = (hv[j].w - mu)*rs*gv.w + bv.w;
        Y4[row*256 + lane + j*32] = o;
    }
}

// ---------------- launch ----------------
extern "C" void kernel_launch(void* const* d_in, const int* in_sizes, int n_in,
                              void* d_out, int out_size) {
    const float* x    = (const float*)d_in[0];
    const float* xnb  = (const float*)d_in[1];
    const int*   mask = (const int*)  d_in[2];
    const float* nm   = (const float*)d_in[3];
    const float* qw   = (const float*)d_in[4];
    const float* qb   = (const float*)d_in[5];
    const float* kw   = (const float*)d_in[6];
    // d_in[7] = kb: cancels in softmax (uniform shift per (b,h) row) -> unused
    const float* vw   = (const float*)d_in[8];
    const float* vb   = (const float*)d_in[9];
    const float* ow   = (const float*)d_in[10];
    const float* ob   = (const float*)d_in[11];
    const float* lg   = (const float*)d_in[12];
    const float* lb   = (const float*)d_in[13];
    float* y = (float*)d_out;

    k_pool   <<<dim3(4, BS), 64>>>(xnb, nm);
    k_q      <<<DIM, 256>>>(qw, qb);
    k_ws     <<<dim3(8, NH), 128>>>(kw);
    k_scores <<<dim3(16, 4, BS), 256>>>(x);
    k_softmax<<<dim3(NH, BS), 256>>>(mask);
    k_xw     <<<dim3(16, 4, BS), 256>>>(x);
    k_xwred  <<<512, 256>>>();
    k_ctx    <<<DIM, 256>>>(vw, vb);
    k_out    <<<DIM, 256>>>(ow, ob);
    k_ln     <<<1024, 256>>>(x, lg, lb, y);
}

// round 7
// speedup vs baseline: 1.1821x; 1.1821x over previous
#include <cuda_runtime.h>
#include <cstdint>

#define BS   8
#define SEQ  1024
#define DIM  1024
#define NH   16
#define HD   64
#define NNB  50

typedef unsigned long long ull;
struct __align__(16) u64x2 { ull a, b; };

__device__ __forceinline__ ull fma2(ull a, ull b, ull c) {
    ull d;
    asm("fma.rn.f32x2 %0, %1, %2, %3;" : "=l"(d) : "l"(a), "l"(b), "l"(c));
    return d;
}
__device__ __forceinline__ ull pack2(float x, float y) {
    ull d;
    asm("mov.b64 %0, {%1, %2};" : "=l"(d) : "f"(x), "f"(y));
    return d;
}
__device__ __forceinline__ float lo32(ull v) { return __uint_as_float((unsigned)(v & 0xffffffffu)); }
__device__ __forceinline__ float hi32(ull v) { return __uint_as_float((unsigned)(v >> 32)); }

// ---------------- scratch (static device globals; no allocation) ----------------
__device__ __align__(16) float g_xn [BS*DIM];           // pooled neighbors
__device__ __align__(16) float g_q  [BS*DIM];           // query projection (already /8)
__device__ __align__(16) float g_ws [BS*NH*DIM];        // per-head score weight vectors
__device__ __align__(16) float g_scp[16][BS*NH*SEQ];    // partial scores (k-split 16)
__device__ __align__(16) float g_w  [BS*NH*SEQ];        // softmax weights
__device__ __align__(16) float g_xwp[16][BS*NH*DIM];    // partial weighted pools (s-split 16)
__device__ __align__(16) float g_xw [BS*NH*DIM];        // weighted pooled x per head
__device__ __align__(16) float g_ctx[BS*DIM];           // context vector per batch
__device__ __align__(16) float g_out[BS*DIM];           // attention output per batch

// ---------------- K1: masked mean-pool. grid (4 dim-chunks, BS), 128 thr, n-split 2 ----------------
__global__ __launch_bounds__(128) void k_pool(const float* __restrict__ xnb,
                                              const float* __restrict__ nm) {
    int b = blockIdx.y;
    int c = blockIdx.x;
    int iloc = threadIdx.x & 63, nh = threadIdx.x >> 6;
    __shared__ float snm[NNB];
    __shared__ __align__(16) float4 part[64];
    if (threadIdx.x < NNB) snm[threadIdx.x] = nm[b*NNB + threadIdx.x];
    __syncthreads();
    float den = 0.f;
    #pragma unroll
    for (int n = 0; n < NNB; n++) den += snm[n];
    float inv = 1.f / den;
    int i = c*256 + iloc*4;
    float4 a = make_float4(0.f, 0.f, 0.f, 0.f);
    int nbeg = nh*25;
    #pragma unroll 5
    for (int n = nbeg; n < nbeg + 25; n++) {
        float4 v = *(const float4*)&xnb[(b*NNB + n)*DIM + i];
        float w = snm[n];
        a.x += v.x*w; a.y += v.y*w; a.z += v.z*w; a.w += v.w*w;
    }
    if (nh == 1) part[iloc] = a;
    __syncthreads();
    if (nh == 0) {
        float4 p = part[iloc];
        a.x = (a.x + p.x)*inv; a.y = (a.y + p.y)*inv;
        a.z = (a.z + p.z)*inv; a.w = (a.w + p.w)*inv;
        *(float4*)&g_xn[b*DIM + i] = a;
    }
}

// ---------------- K2: q[b,j] = (qw[j,:]·xn[b,:] + qb[j]) / 8 ----------------
__global__ __launch_bounds__(256) void k_q(const float* __restrict__ qw,
                                           const float* __restrict__ qb) {
    int j = blockIdx.x;
    float p[BS];
    #pragma unroll
    for (int b = 0; b < BS; b++) p[b] = 0.f;
    #pragma unroll
    for (int it = 0; it < 4; it++) {
        int i = threadIdx.x + it*256;
        float wv = qw[j*DIM + i];
        #pragma unroll
        for (int b = 0; b < BS; b++) p[b] += wv * g_xn[b*DIM + i];
    }
    #pragma unroll
    for (int off = 16; off; off >>= 1)
        #pragma unroll
        for (int b = 0; b < BS; b++) p[b] += __shfl_down_sync(0xffffffffu, p[b], off);
    __shared__ float red[8][BS];
    int w = threadIdx.x >> 5, lane = threadIdx.x & 31;
    if (lane == 0) {
        #pragma unroll
        for (int b = 0; b < BS; b++) red[w][b] = p[b];
    }
    __syncthreads();
    if (threadIdx.x < BS) {
        int b = threadIdx.x;
        float s = 0.f;
        #pragma unroll
        for (int w2 = 0; w2 < 8; w2++) s += red[w2][b];
        g_q[b*DIM + j] = (s + qb[j]) * 0.125f;
    }
}

// ---------------- K3: ws[b,h,i]. grid (16 ic, 16 h), 128 thr, jj-split 2 ----------------
__global__ __launch_bounds__(128) void k_ws(const float* __restrict__ kw) {
    int ic = blockIdx.x;               // 0..15 -> i-range 64
    int h  = blockIdx.y;
    int iloc = threadIdx.x & 63, jh = threadIdx.x >> 6;
    int i  = ic*64 + iloc;
    __shared__ float qs[BS][HD];
    __shared__ float part[BS][64];
    for (int e = threadIdx.x; e < BS*HD; e += 128) {
        int b = e >> 6, jj = e & 63;
        qs[b][jj] = g_q[b*DIM + h*HD + jj];
    }
    __syncthreads();
    float acc[BS];
    #pragma unroll
    for (int b = 0; b < BS; b++) acc[b] = 0.f;
    int jbeg = jh*32;
    #pragma unroll 4
    for (int jj = jbeg; jj < jbeg + 32; jj++) {
        float kwv = kw[(h*HD + jj)*DIM + i];
        #pragma unroll
        for (int b = 0; b < BS; b++) acc[b] += qs[b][jj] * kwv;
    }
    if (jh == 1) {
        #pragma unroll
        for (int b = 0; b < BS; b++) part[b][iloc] = acc[b];
    }
    __syncthreads();
    if (jh == 0) {
        #pragma unroll
        for (int b = 0; b < BS; b++)
            g_ws[(b*NH + h)*DIM + i] = acc[b] + part[b][iloc];
    }
}

// ---------------- K4: partial scores. grid (16 ksplit, 8 stile, 8 b), 128 thr ----------------
// R5 structure; inner loop uses f32x2 on s-adjacent pairs (14 issues/kk vs 18).
__global__ __launch_bounds__(128) void k_scores(const float* __restrict__ x) {
    int ks = blockIdx.x;           // k range [ks*64, ks*64+64)
    int st = blockIdx.y;           // 128 seq rows
    int b  = blockIdx.z;
    int s0 = st*128, k0 = ks*64;
    __shared__ __align__(16) float xs [16*132];   // [kk][128 s + pad4]
    __shared__ __align__(16) float wss[16*20];    // [kk][16 h + pad4]
    int tid = threadIdx.x;
    int hg = tid >> 5;             // 0..3 -> heads hg*4..hg*4+3 (constant per warp)
    int sq = tid & 31;             // seq cols sq*4..sq*4+3
    ull a0p0=0,a0p1=0, a1p0=0,a1p1=0, a2p0=0,a2p1=0, a3p0=0,a3p1=0;

    #pragma unroll
    for (int kc = 0; kc < 4; kc++) {
        int kb = k0 + kc*16;
        #pragma unroll
        for (int it = 0; it < 4; it++) {
            int e = tid + it*128;          // 0..511
            int kk4 = e & 3, ss = e >> 2;  // float4 along k
            float4 v = *(const float4*)&x[(b*SEQ + s0 + ss)*DIM + kb + kk4*4];
            xs[(kk4*4+0)*132 + ss] = v.x;
            xs[(kk4*4+1)*132 + ss] = v.y;
            xs[(kk4*4+2)*132 + ss] = v.z;
            xs[(kk4*4+3)*132 + ss] = v.w;
        }
        #pragma unroll
        for (int it = 0; it < 2; it++) {
            int e = tid + it*128;
            int kk = e & 15, h = e >> 4;
            wss[kk*20 + h] = g_ws[(b*NH + h)*DIM + kb + kk];
        }
        __syncthreads();
        #pragma unroll
        for (int kk = 0; kk < 16; kk++) {
            u64x2 xp = *(const u64x2*)&xs[kk*132 + sq*4];  // (s0,s1),(s2,s3)
            float4 wv = *(const float4*)&wss[kk*20 + hg*4];
            ull w0 = pack2(wv.x, wv.x);
            ull w1 = pack2(wv.y, wv.y);
            ull w2 = pack2(wv.z, wv.z);
            ull w3 = pack2(wv.w, wv.w);
            a0p0 = fma2(w0, xp.a, a0p0); a0p1 = fma2(w0, xp.b, a0p1);
            a1p0 = fma2(w1, xp.a, a1p0); a1p1 = fma2(w1, xp.b, a1p1);
            a2p0 = fma2(w2, xp.a, a2p0); a2p1 = fma2(w2, xp.b, a2p1);
            a3p0 = fma2(w3, xp.a, a3p0); a3p1 = fma2(w3, xp.b, a3p1);
        }
        __syncthreads();
    }
    float* dst = g_scp[ks];
    ull accp[4][2] = {{a0p0,a0p1},{a1p0,a1p1},{a2p0,a2p1},{a3p0,a3p1}};
    #pragma unroll
    for (int j = 0; j < 4; j++) {
        int r = (b*NH + hg*4 + j)*SEQ + s0 + sq*4;
        *(float4*)&dst[r] = make_float4(lo32(accp[j][0]), hi32(accp[j][0]),
                                        lo32(accp[j][1]), hi32(accp[j][1]));
    }
}

// ---------------- K5: softmax over seq per (b,h); sums the 16 k-split partials ----------------
__global__ __launch_bounds__(256) void k_softmax(const int* __restrict__ mask) {
    int h = blockIdx.x, b = blockIdx.y;
    int base = (b*NH + h)*SEQ;
    int tid = threadIdx.x;
    float v[4];
    float m = -3.4e38f;
    #pragma unroll
    for (int t = 0; t < 4; t++) {
        int s = tid + t*256;
        float sc = 0.f;
        #pragma unroll
        for (int ks = 0; ks < 16; ks++) sc += g_scp[ks][base + s];
        if (mask[b*SEQ + s] == 0) sc = -1e30f;
        v[t] = sc;
        m = fmaxf(m, sc);
    }
    __shared__ float sred[8];
    int w = tid >> 5, lane = tid & 31;
    #pragma unroll
    for (int off = 16; off; off >>= 1) m = fmaxf(m, __shfl_xor_sync(0xffffffffu, m, off));
    if (lane == 0) sred[w] = m;
    __syncthreads();
    float m0 = sred[0];
    #pragma unroll
    for (int w2 = 1; w2 < 8; w2++) m0 = fmaxf(m0, sred[w2]);
    __syncthreads();
    float sum = 0.f;
    #pragma unroll
    for (int t = 0; t < 4; t++) { v[t] = expf(v[t] - m0); sum += v[t]; }
    #pragma unroll
    for (int off = 16; off; off >>= 1) sum += __shfl_xor_sync(0xffffffffu, sum, off);
    if (lane == 0) sred[w] = sum;
    __syncthreads();
    float tot = 0.f;
    #pragma unroll
    for (int w2 = 0; w2 < 8; w2++) tot += sred[w2];
    float inv = 1.f / tot;
    #pragma unroll
    for (int t = 0; t < 4; t++) g_w[base + tid + t*256] = v[t] * inv;
}

// ---------------- K6: partial weighted pools. grid (16 schunk, 4 ichunk, 8 b), f32x2 ----------------
__global__ __launch_bounds__(256) void k_xw(const float* __restrict__ x) {
    int sc = blockIdx.x;   // seq chunk (64)
    int ic = blockIdx.y;   // dim chunk (256)
    int b  = blockIdx.z;
    int i  = ic*256 + threadIdx.x;
    __shared__ __align__(16) float wt[64*20];   // [s][16 h + pad4]
    for (int e = threadIdx.x; e < 1024; e += 256) {
        int s = e & 63, h = e >> 6;
        wt[s*20 + h] = g_w[(b*NH + h)*SEQ + sc*64 + s];
    }
    __syncthreads();
    ull acc[8];
    #pragma unroll
    for (int p = 0; p < 8; p++) acc[p] = 0ull;
    const float* xp = &x[(b*SEQ + sc*64)*DIM + i];
    #pragma unroll 8
    for (int ss = 0; ss < 64; ss++) {
        float xv = xp[ss*DIM];
        ull xd = pack2(xv, xv);
        const float* wr = &wt[ss*20];
        u64x2 w0 = *(const u64x2*)&wr[0];
        u64x2 w1 = *(const u64x2*)&wr[4];
        u64x2 w2 = *(const u64x2*)&wr[8];
        u64x2 w3 = *(const u64x2*)&wr[12];
        acc[0] = fma2(w0.a, xd, acc[0]); acc[1] = fma2(w0.b, xd, acc[1]);
        acc[2] = fma2(w1.a, xd, acc[2]); acc[3] = fma2(w1.b, xd, acc[3]);
        acc[4] = fma2(w2.a, xd, acc[4]); acc[5] = fma2(w2.b, xd, acc[5]);
        acc[6] = fma2(w3.a, xd, acc[6]); acc[7] = fma2(w3.b, xd, acc[7]);
    }
    float* dst = g_xwp[sc];
    #pragma unroll
    for (int p = 0; p < 8; p++) {
        dst[(b*NH + 2*p  )*DIM + i] = lo32(acc[p]);
        dst[(b*NH + 2*p+1)*DIM + i] = hi32(acc[p]);
    }
}

// ---------------- K6b: reduce the 16 seq-chunk partials ----------------
__global__ __launch_bounds__(256) void k_xwred() {
    int idx = blockIdx.x*256 + threadIdx.x;   // 512 blocks -> 131072
    float s = 0.f;
    #pragma unroll
    for (int sc = 0; sc < 16; sc++) s += g_xwp[sc][idx];
    g_xw[idx] = s;
}

// ---------------- K7a: context[b,j] = vw[j,:]·xw[b, j/64, :] + vb[j] ----------------
__global__ __launch_bounds__(256) void k_ctx(const float* __restrict__ vw,
                                             const float* __restrict__ vb) {
    int j = blockIdx.x;
    int h = j >> 6;
    float p[BS];
    #pragma unroll
    for (int b = 0; b < BS; b++) p[b] = 0.f;
    #pragma unroll
    for (int it = 0; it < 4; it++) {
        int i = threadIdx.x + it*256;
        float wv = vw[j*DIM + i];
        #pragma unroll
        for (int b = 0; b < BS; b++) p[b] += wv * g_xw[(b*NH + h)*DIM + i];
    }
    #pragma unroll
    for (int off = 16; off; off >>= 1)
        #pragma unroll
        for (int b = 0; b < BS; b++) p[b] += __shfl_down_sync(0xffffffffu, p[b], off);
    __shared__ float red[8][BS];
    int w = threadIdx.x >> 5, lane = threadIdx.x & 31;
    if (lane == 0) {
        #pragma unroll
        for (int b = 0; b < BS; b++) red[w][b] = p[b];
    }
    __syncthreads();
    if (threadIdx.x < BS) {
        int b = threadIdx.x;
        float s = 0.f;
        #pragma unroll
        for (int w2 = 0; w2 < 8; w2++) s += red[w2][b];
        g_ctx[b*DIM + j] = s + vb[j];
    }
}

// ---------------- K7b: out[b,j] = ow[j,:]·ctx[b,:] + ob[j] ----------------
__global__ __launch_bounds__(256) void k_out(const float* __restrict__ ow,
                                             const float* __restrict__ ob) {
    int j = blockIdx.x;
    float p[BS];
    #pragma unroll
    for (int b = 0; b < BS; b++) p[b] = 0.f;
    #pragma unroll
    for (int it = 0; it < 4; it++) {
        int i = threadIdx.x + it*256;
        float wv = ow[j*DIM + i];
        #pragma unroll
        for (int b = 0; b < BS; b++) p[b] += wv * g_ctx[b*DIM + i];
    }
    #pragma unroll
    for (int off = 16; off; off >>= 1)
        #pragma unroll
        for (int b = 0; b < BS; b++) p[b] += __shfl_down_sync(0xffffffffu, p[b], off);
    __shared__ float red[8][BS];
    int w = threadIdx.x >> 5, lane = threadIdx.x & 31;
    if (lane == 0) {
        #pragma unroll
        for (int b = 0; b < BS; b++) red[w][b] = p[b];
    }
    __syncthreads();
    if (threadIdx.x < BS) {
        int b = threadIdx.x;
        float s = 0.f;
        #pragma unroll
        for (int w2 = 0; w2 < 8; w2++) s += red[w2][b];
        g_out[b*DIM + j] = s + ob[j];
    }
}

// ---------------- K8: y[b,s,:] = LN(x[b,s,:] + out[b,:]) * g + beta ----------------
__global__ __launch_bounds__(256) void k_ln(const float* __restrict__ x,
                                            const float* __restrict__ lg,
                                            const float* __restrict__ lb,
                                            float* __restrict__ y) {
    int row  = blockIdx.x*8 + (threadIdx.x >> 5);   // 8192 rows, warp per row
    int lane = threadIdx.x & 31;
    int b    = row >> 10;
    const float4* X4 = (const float4*)x;
    const float4* O4 = (const float4*)g_out;
    float4 hv[8];
    float sum = 0.f, sq = 0.f;
    #pragma unroll
    for (int j = 0; j < 8; j++) {
        float4 xv = X4[row*256 + lane + j*32];
        float4 ov = O4[b*256  + lane + j*32];
        float4 h;
        h.x = xv.x + ov.x; h.y = xv.y + ov.y; h.z = xv.z + ov.z; h.w = xv.w + ov.w;
        hv[j] = h;
        sum += h.x + h.y + h.z + h.w;
        sq  += h.x*h.x + h.y*h.y + h.z*h.z + h.w*h.w;
    }
    #pragma unroll
    for (int off = 16; off; off >>= 1) {
        sum += __shfl_xor_sync(0xffffffffu, sum, off);
        sq  += __shfl_xor_sync(0xffffffffu, sq,  off);
    }
    float mu  = sum * (1.f/1024.f);
    float var = sq  * (1.f/1024.f) - mu*mu;
    float rs  = rsqrtf(var + 1e-12f);
    const float4* G4 = (const float4*)lg;
    const float4* B4 = (const float4*)lb;
    float4* Y4 = (float4*)y;
    #pragma unroll
    for (int j = 0; j < 8; j++) {
        float4 gv = G4[lane + j*32];
        float4 bv = B4[lane + j*32];
        float4 o;
        o.x = (hv[j].x - mu)*rs*gv.x + bv.x;
        o.y = (hv[j].y - mu)*rs*gv.y + bv.y;
        o.z = (hv[j].z - mu)*rs*gv.z + bv.z;
        o.w = (hv[j].w - mu)*rs*gv.w + bv.w;
        Y4[row*256 + lane + j*32] = o;
    }
}

// ---------------- launch ----------------
extern "C" void kernel_launch(void* const* d_in, const int* in_sizes, int n_in,
                              void* d_out, int out_size) {
    const float* x    = (const float*)d_in[0];
    const float* xnb  = (const float*)d_in[1];
    const int*   mask = (const int*)  d_in[2];
    const float* nm   = (const float*)d_in[3];
    const float* qw   = (const float*)d_in[4];
    const float* qb   = (const float*)d_in[5];
    const float* kw   = (const float*)d_in[6];
    // d_in[7] = kb: cancels in softmax (uniform shift per (b,h) row) -> unused
    const float* vw   = (const float*)d_in[8];
    const float* vb   = (const float*)d_in[9];
    const float* ow   = (const float*)d_in[10];
    const float* ob   = (const float*)d_in[11];
    const float* lg   = (const float*)d_in[12];
    const float* lb   = (const float*)d_in[13];
    float* y = (float*)d_out;

    k_pool   <<<dim3(4, BS), 128>>>(xnb, nm);
    k_q      <<<DIM, 256>>>(qw, qb);
    k_ws     <<<dim3(16, NH), 128>>>(kw);
    k_scores <<<dim3(16, 8, BS), 128>>>(x);
    k_softmax<<<dim3(NH, BS), 256>>>(mask);
    k_xw     <<<dim3(16, 4, BS), 256>>>(x);
    k_xwred  <<<512, 256>>>();
    k_ctx    <<<DIM, 256>>>(vw, vb);
    k_out    <<<DIM, 256>>>(ow, ob);
    k_ln     <<<1024, 256>>>(x, lg, lb, y);
}

// round 10
// speedup vs baseline: 1.2367x; 1.0462x over previous
#include <cuda_runtime.h>
#include <cstdint>

#define BS   8
#define SEQ  1024
#define DIM  1024
#define NH   16
#define HD   64
#define NNB  50

typedef unsigned long long ull;
struct __align__(16) u64x2 { ull a, b; };

__device__ __forceinline__ ull fma2(ull a, ull b, ull c) {
    ull d;
    asm("fma.rn.f32x2 %0, %1, %2, %3;" : "=l"(d) : "l"(a), "l"(b), "l"(c));
    return d;
}
__device__ __forceinline__ ull pack2(float x, float y) {
    ull d;
    asm("mov.b64 %0, {%1, %2};" : "=l"(d) : "f"(x), "f"(y));
    return d;
}
__device__ __forceinline__ float lo32(ull v) { return __uint_as_float((unsigned)(v & 0xffffffffu)); }
__device__ __forceinline__ float hi32(ull v) { return __uint_as_float((unsigned)(v >> 32)); }

// ---------------- scratch (static device globals; no allocation) ----------------
__device__ __align__(16) float g_xn [BS*DIM];           // pooled neighbors
__device__ __align__(16) float g_q  [BS*DIM];           // query projection (already /8)
__device__ __align__(16) float g_ws [BS*NH*DIM];        // per-head score weight vectors
__device__ __align__(16) float g_scp[16][BS*NH*SEQ];    // partial scores (k-split 16)
__device__ __align__(16) float g_w  [BS*NH*SEQ];        // softmax weights
__device__ __align__(16) float g_xwp[16][BS*NH*DIM];    // partial weighted pools (s-split 16)
__device__ __align__(16) float g_xw [BS*NH*DIM];        // weighted pooled x per head
__device__ __align__(16) float g_ctx[BS*DIM];           // context vector per batch
__device__ __align__(16) float g_out[BS*DIM];           // attention output per batch

// ---------------- K1: masked mean-pool. grid (4 dim-chunks, BS), 128 thr, n-split 2 ----------------
__global__ __launch_bounds__(128) void k_pool(const float* __restrict__ xnb,
                                              const float* __restrict__ nm) {
    int b = blockIdx.y;
    int c = blockIdx.x;
    int iloc = threadIdx.x & 63, nh = threadIdx.x >> 6;
    __shared__ float snm[NNB];
    __shared__ __align__(16) float4 part[64];
    if (threadIdx.x < NNB) snm[threadIdx.x] = nm[b*NNB + threadIdx.x];
    __syncthreads();
    float den = 0.f;
    #pragma unroll
    for (int n = 0; n < NNB; n++) den += snm[n];
    float inv = 1.f / den;
    int i = c*256 + iloc*4;
    float4 a = make_float4(0.f, 0.f, 0.f, 0.f);
    int nbeg = nh*25;
    #pragma unroll 5
    for (int n = nbeg; n < nbeg + 25; n++) {
        float4 v = *(const float4*)&xnb[(b*NNB + n)*DIM + i];
        float w = snm[n];
        a.x += v.x*w; a.y += v.y*w; a.z += v.z*w; a.w += v.w*w;
    }
    if (nh == 1) part[iloc] = a;
    __syncthreads();
    if (nh == 0) {
        float4 p = part[iloc];
        a.x = (a.x + p.x)*inv; a.y = (a.y + p.y)*inv;
        a.z = (a.z + p.z)*inv; a.w = (a.w + p.w)*inv;
        *(float4*)&g_xn[b*DIM + i] = a;
    }
}

// ---------------- K2: q[b,j] = (qw[j,:]·xn[b,:] + qb[j]) / 8 ----------------
__global__ __launch_bounds__(256) void k_q(const float* __restrict__ qw,
                                           const float* __restrict__ qb) {
    int j = blockIdx.x;
    float p[BS];
    #pragma unroll
    for (int b = 0; b < BS; b++) p[b] = 0.f;
    #pragma unroll
    for (int it = 0; it < 4; it++) {
        int i = threadIdx.x + it*256;
        float wv = qw[j*DIM + i];
        #pragma unroll
        for (int b = 0; b < BS; b++) p[b] += wv * g_xn[b*DIM + i];
    }
    #pragma unroll
    for (int off = 16; off; off >>= 1)
        #pragma unroll
        for (int b = 0; b < BS; b++) p[b] += __shfl_down_sync(0xffffffffu, p[b], off);
    __shared__ float red[8][BS];
    int w = threadIdx.x >> 5, lane = threadIdx.x & 31;
    if (lane == 0) {
        #pragma unroll
        for (int b = 0; b < BS; b++) red[w][b] = p[b];
    }
    __syncthreads();
    if (threadIdx.x < BS) {
        int b = threadIdx.x;
        float s = 0.f;
        #pragma unroll
        for (int w2 = 0; w2 < 8; w2++) s += red[w2][b];
        g_q[b*DIM + j] = (s + qb[j]) * 0.125f;
    }
}

// ---------------- K3: ws[b,h,i]. grid (16 ic, 16 h), 128 thr, jj-split 2 ----------------
__global__ __launch_bounds__(128) void k_ws(const float* __restrict__ kw) {
    int ic = blockIdx.x;               // 0..15 -> i-range 64
    int h  = blockIdx.y;
    int iloc = threadIdx.x & 63, jh = threadIdx.x >> 6;
    int i  = ic*64 + iloc;
    __shared__ float qs[BS][HD];
    __shared__ float part[BS][64];
    for (int e = threadIdx.x; e < BS*HD; e += 128) {
        int b = e >> 6, jj = e & 63;
        qs[b][jj] = g_q[b*DIM + h*HD + jj];
    }
    __syncthreads();
    float acc[BS];
    #pragma unroll
    for (int b = 0; b < BS; b++) acc[b] = 0.f;
    int jbeg = jh*32;
    #pragma unroll 4
    for (int jj = jbeg; jj < jbeg + 32; jj++) {
        float kwv = kw[(h*HD + jj)*DIM + i];
        #pragma unroll
        for (int b = 0; b < BS; b++) acc[b] += qs[b][jj] * kwv;
    }
    if (jh == 1) {
        #pragma unroll
        for (int b = 0; b < BS; b++) part[b][iloc] = acc[b];
    }
    __syncthreads();
    if (jh == 0) {
        #pragma unroll
        for (int b = 0; b < BS; b++)
            g_ws[(b*NH + h)*DIM + i] = acc[b] + part[b][iloc];
    }
}

// ---------------- K4: partial scores. grid (16 ksplit, 8 stile, 8 b), 128 thr ----------------
// Single-shot staging: whole 64k x 128s tile loaded with MLP~16, ONE barrier,
// then 64 uninterrupted kk iterations of smem-fed FFMA2.
__global__ __launch_bounds__(128, 5) void k_scores(const float* __restrict__ x) {
    int ks = blockIdx.x;           // k range [ks*64, ks*64+64)
    int st = blockIdx.y;           // 128 seq rows
    int b  = blockIdx.z;
    int s0 = st*128, k0 = ks*64;
    __shared__ __align__(16) float xs [64*132];   // [kk][128 s + pad4]  33.8 KB
    __shared__ __align__(16) float wss[64*20];    // [kk][16 h + pad4]    5.1 KB
    int tid = threadIdx.x;
    int hg = tid >> 5;             // heads hg*4..hg*4+3 (constant per warp)
    int sq = tid & 31;             // seq cols sq*4..sq*4+3

    const float* xbase = &x[(b*SEQ + s0)*DIM + k0];
    const float* wbase = &g_ws[b*NH*DIM + k0];

    // ---- stage A: 8 x-float4 + all 8 ws scalars (16 outstanding loads) ----
    float4 va[8]; float wv[8];
    #pragma unroll
    for (int it = 0; it < 8; it++) {
        int e = tid + it*128;            // 0..1023
        int kk4 = e & 15, ss = e >> 4;   // ss 0..63
        va[it] = *(const float4*)&xbase[ss*DIM + kk4*4];
    }
    #pragma unroll
    for (int it = 0; it < 8; it++) {
        int e = tid + it*128;            // 0..1023
        int kk = e & 63, h = e >> 6;
        wv[it] = wbase[h*DIM + kk];
    }
    #pragma unroll
    for (int it = 0; it < 8; it++) {
        int e = tid + it*128;
        int kk4 = e & 15, ss = e >> 4;
        xs[(kk4*4+0)*132 + ss] = va[it].x;
        xs[(kk4*4+1)*132 + ss] = va[it].y;
        xs[(kk4*4+2)*132 + ss] = va[it].z;
        xs[(kk4*4+3)*132 + ss] = va[it].w;
    }
    #pragma unroll
    for (int it = 0; it < 8; it++) {
        int e = tid + it*128;
        int kk = e & 63, h = e >> 6;
        wss[kk*20 + h] = wv[it];
    }
    // ---- stage B: remaining 8 x-float4 ----
    #pragma unroll
    for (int it = 0; it < 8; it++) {
        int e = tid + (it+8)*128;        // 1024..2047
        int kk4 = e & 15, ss = e >> 4;   // ss 64..127
        va[it] = *(const float4*)&xbase[ss*DIM + kk4*4];
    }
    #pragma unroll
    for (int it = 0; it < 8; it++) {
        int e = tid + (it+8)*128;
        int kk4 = e & 15, ss = e >> 4;
        xs[(kk4*4+0)*132 + ss] = va[it].x;
        xs[(kk4*4+1)*132 + ss] = va[it].y;
        xs[(kk4*4+2)*132 + ss] = va[it].z;
        xs[(kk4*4+3)*132 + ss] = va[it].w;
    }
    __syncthreads();

    ull a0p0=0,a0p1=0, a1p0=0,a1p1=0, a2p0=0,a2p1=0, a3p0=0,a3p1=0;
    #pragma unroll 16
    for (int kk = 0; kk < 64; kk++) {
        u64x2 xp = *(const u64x2*)&xs[kk*132 + sq*4];  // (s0,s1),(s2,s3)
        float4 wv4 = *(const float4*)&wss[kk*20 + hg*4];
        ull w0 = pack2(wv4.x, wv4.x);
        ull w1 = pack2(wv4.y, wv4.y);
        ull w2 = pack2(wv4.z, wv4.z);
        ull w3 = pack2(wv4.w, wv4.w);
        a0p0 = fma2(w0, xp.a, a0p0); a0p1 = fma2(w0, xp.b, a0p1);
        a1p0 = fma2(w1, xp.a, a1p0); a1p1 = fma2(w1, xp.b, a1p1);
        a2p0 = fma2(w2, xp.a, a2p0); a2p1 = fma2(w2, xp.b, a2p1);
        a3p0 = fma2(w3, xp.a, a3p0); a3p1 = fma2(w3, xp.b, a3p1);
    }

    float* dst = g_scp[ks];
    ull accp[4][2] = {{a0p0,a0p1},{a1p0,a1p1},{a2p0,a2p1},{a3p0,a3p1}};
    #pragma unroll
    for (int j = 0; j < 4; j++) {
        int r = (b*NH + hg*4 + j)*SEQ + s0 + sq*4;
        *(float4*)&dst[r] = make_float4(lo32(accp[j][0]), hi32(accp[j][0]),
                                        lo32(accp[j][1]), hi32(accp[j][1]));
    }
}

// ---------------- K5: softmax over seq per (b,h); sums the 16 k-split partials ----------------
__global__ __launch_bounds__(256) void k_softmax(const int* __restrict__ mask) {
    int h = blockIdx.x, b = blockIdx.y;
    int base = (b*NH + h)*SEQ;
    int tid = threadIdx.x;
    float v[4];
    float m = -3.4e38f;
    #pragma unroll
    for (int t = 0; t < 4; t++) {
        int s = tid + t*256;
        float sc = 0.f;
        #pragma unroll
        for (int ks = 0; ks < 16; ks++) sc += g_scp[ks][base + s];
        if (mask[b*SEQ + s] == 0) sc = -1e30f;
        v[t] = sc;
        m = fmaxf(m, sc);
    }
    __shared__ float sred[8];
    int w = tid >> 5, lane = tid & 31;
    #pragma unroll
    for (int off = 16; off; off >>= 1) m = fmaxf(m, __shfl_xor_sync(0xffffffffu, m, off));
    if (lane == 0) sred[w] = m;
    __syncthreads();
    float m0 = sred[0];
    #pragma unroll
    for (int w2 = 1; w2 < 8; w2++) m0 = fmaxf(m0, sred[w2]);
    __syncthreads();
    float sum = 0.f;
    #pragma unroll
    for (int t = 0; t < 4; t++) { v[t] = expf(v[t] - m0); sum += v[t]; }
    #pragma unroll
    for (int off = 16; off; off >>= 1) sum += __shfl_xor_sync(0xffffffffu, sum, off);
    if (lane == 0) sred[w] = sum;
    __syncthreads();
    float tot = 0.f;
    #pragma unroll
    for (int w2 = 0; w2 < 8; w2++) tot += sred[w2];
    float inv = 1.f / tot;
    #pragma unroll
    for (int t = 0; t < 4; t++) g_w[base + tid + t*256] = v[t] * inv;
}

// ---------------- K6: partial weighted pools. grid (16 schunk, 4 ichunk, 8 b), f32x2 ----------------
__global__ __launch_bounds__(256) void k_xw(const float* __restrict__ x) {
    int sc = blockIdx.x;   // seq chunk (64)
    int ic = blockIdx.y;   // dim chunk (256)
    int b  = blockIdx.z;
    int i  = ic*256 + threadIdx.x;
    __shared__ __align__(16) float wt[64*20];   // [s][16 h + pad4]
    for (int e = threadIdx.x; e < 1024; e += 256) {
        int s = e & 63, h = e >> 6;
        wt[s*20 + h] = g_w[(b*NH + h)*SEQ + sc*64 + s];
    }
    __syncthreads();
    ull acc[8];
    #pragma unroll
    for (int p = 0; p < 8; p++) acc[p] = 0ull;
    const float* xp = &x[(b*SEQ + sc*64)*DIM + i];
    #pragma unroll 16
    for (int ss = 0; ss < 64; ss++) {
        float xv = xp[ss*DIM];
        ull xd = pack2(xv, xv);
        const float* wr = &wt[ss*20];
        u64x2 w0 = *(const u64x2*)&wr[0];
        u64x2 w1 = *(const u64x2*)&wr[4];
        u64x2 w2 = *(const u64x2*)&wr[8];
        u64x2 w3 = *(const u64x2*)&wr[12];
        acc[0] = fma2(w0.a, xd, acc[0]); acc[1] = fma2(w0.b, xd, acc[1]);
        acc[2] = fma2(w1.a, xd, acc[2]); acc[3] = fma2(w1.b, xd, acc[3]);
        acc[4] = fma2(w2.a, xd, acc[4]); acc[5] = fma2(w2.b, xd, acc[5]);
        acc[6] = fma2(w3.a, xd, acc[6]); acc[7] = fma2(w3.b, xd, acc[7]);
    }
    float* dst = g_xwp[sc];
    #pragma unroll
    for (int p = 0; p < 8; p++) {
        dst[(b*NH + 2*p  )*DIM + i] = lo32(acc[p]);
        dst[(b*NH + 2*p+1)*DIM + i] = hi32(acc[p]);
    }
}

// ---------------- K6b: reduce the 16 seq-chunk partials ----------------
__global__ __launch_bounds__(256) void k_xwred() {
    int idx = blockIdx.x*256 + threadIdx.x;   // 512 blocks -> 131072
    float s = 0.f;
    #pragma unroll
    for (int sc = 0; sc < 16; sc++) s += g_xwp[sc][idx];
    g_xw[idx] = s;
}

// ---------------- K7a: context[b,j] = vw[j,:]·xw[b, j/64, :] + vb[j] ----------------
__global__ __launch_bounds__(256) void k_ctx(const float* __restrict__ vw,
                                             const float* __restrict__ vb) {
    int j = blockIdx.x;
    int h = j >> 6;
    float p[BS];
    #pragma unroll
    for (int b = 0; b < BS; b++) p[b] = 0.f;
    #pragma unroll
    for (int it = 0; it < 4; it++) {
        int i = threadIdx.x + it*256;
        float wv = vw[j*DIM + i];
        #pragma unroll
        for (int b = 0; b < BS; b++) p[b] += wv * g_xw[(b*NH + h)*DIM + i];
    }
    #pragma unroll
    for (int off = 16; off; off >>= 1)
        #pragma unroll
        for (int b = 0; b < BS; b++) p[b] += __shfl_down_sync(0xffffffffu, p[b], off);
    __shared__ float red[8][BS];
    int w = threadIdx.x >> 5, lane = threadIdx.x & 31;
    if (lane == 0) {
        #pragma unroll
        for (int b = 0; b < BS; b++) red[w][b] = p[b];
    }
    __syncthreads();
    if (threadIdx.x < BS) {
        int b = threadIdx.x;
        float s = 0.f;
        #pragma unroll
        for (int w2 = 0; w2 < 8; w2++) s += red[w2][b];
        g_ctx[b*DIM + j] = s + vb[j];
    }
}

// ---------------- K7b: out[b,j] = ow[j,:]·ctx[b,:] + ob[j] ----------------
__global__ __launch_bounds__(256) void k_out(const float* __restrict__ ow,
                                             const float* __restrict__ ob) {
    int j = blockIdx.x;
    float p[BS];
    #pragma unroll
    for (int b = 0; b < BS; b++) p[b] = 0.f;
    #pragma unroll
    for (int it = 0; it < 4; it++) {
        int i = threadIdx.x + it*256;
        float wv = ow[j*DIM + i];
        #pragma unroll
        for (int b = 0; b < BS; b++) p[b] += wv * g_ctx[b*DIM + i];
    }
    #pragma unroll
    for (int off = 16; off; off >>= 1)
        #pragma unroll
        for (int b = 0; b < BS; b++) p[b] += __shfl_down_sync(0xffffffffu, p[b], off);
    __shared__ float red[8][BS];
    int w = threadIdx.x >> 5, lane = threadIdx.x & 31;
    if (lane == 0) {
        #pragma unroll
        for (int b = 0; b < BS; b++) red[w][b] = p[b];
    }
    __syncthreads();
    if (threadIdx.x < BS) {
        int b = threadIdx.x;
        float s = 0.f;
        #pragma unroll
        for (int w2 = 0; w2 < 8; w2++) s += red[w2][b];
        g_out[b*DIM + j] = s + ob[j];
    }
}

// ---------------- K8: y[b,s,:] = LN(x[b,s,:] + out[b,:]) * g + beta ----------------
__global__ __launch_bounds__(256) void k_ln(const float* __restrict__ x,
                                            const float* __restrict__ lg,
                                            const float* __restrict__ lb,
                                            float* __restrict__ y) {
    int row  = blockIdx.x*8 + (threadIdx.x >> 5);   // 8192 rows, warp per row
    int lane = threadIdx.x & 31;
    int b    = row >> 10;
    const float4* X4 = (const float4*)x;
    const float4* O4 = (const float4*)g_out;
    float4 hv[8];
    float sum = 0.f, sq = 0.f;
    #pragma unroll
    for (int j = 0; j < 8; j++) {
        float4 xv = X4[row*256 + lane + j*32];
        float4 ov = O4[b*256  + lane + j*32];
        float4 h;
        h.x = xv.x + ov.x; h.y = xv.y + ov.y; h.z = xv.z + ov.z; h.w = xv.w + ov.w;
        hv[j] = h;
        sum += h.x + h.y + h.z + h.w;
        sq  += h.x*h.x + h.y*h.y + h.z*h.z + h.w*h.w;
    }
    #pragma unroll
    for (int off = 16; off; off >>= 1) {
        sum += __shfl_xor_sync(0xffffffffu, sum, off);
        sq  += __shfl_xor_sync(0xffffffffu, sq,  off);
    }
    float mu  = sum * (1.f/1024.f);
    float var = sq  * (1.f/1024.f) - mu*mu;
    float rs  = rsqrtf(var + 1e-12f);
    const float4* G4 = (const float4*)lg;
    const float4* B4 = (const float4*)lb;
    float4* Y4 = (float4*)y;
    #pragma unroll
    for (int j = 0; j < 8; j++) {
        float4 gv = G4[lane + j*32];
        float4 bv = B4[lane + j*32];
        float4 o;
        o.x = (hv[j].x - mu)*rs*gv.x + bv.x;
        o.y = (hv[j].y - mu)*rs*gv.y + bv.y;
        o.z = (hv[j].z - mu)*rs*gv.z + bv.z;
        o.w = (hv[j].w - mu)*rs*gv.w + bv.w;
        Y4[row*256 + lane + j*32] = o;
    }
}

// ---------------- launch ----------------
extern "C" void kernel_launch(void* const* d_in, const int* in_sizes, int n_in,
                              void* d_out, int out_size) {
    const float* x    = (const float*)d_in[0];
    const float* xnb  = (const float*)d_in[1];
    const int*   mask = (const int*)  d_in[2];
    const float* nm   = (const float*)d_in[3];
    const float* qw   = (const float*)d_in[4];
    const float* qb   = (const float*)d_in[5];
    const float* kw   = (const float*)d_in[6];
    // d_in[7] = kb: cancels in softmax (uniform shift per (b,h) row) -> unused
    const float* vw   = (const float*)d_in[8];
    const float* vb   = (const float*)d_in[9];
    const float* ow   = (const float*)d_in[10];
    const float* ob   = (const float*)d_in[11];
    const float* lg   = (const float*)d_in[12];
    const float* lb   = (const float*)d_in[13];
    float* y = (float*)d_out;

    k_pool   <<<dim3(4, BS), 128>>>(xnb, nm);
    k_q      <<<DIM, 256>>>(qw, qb);
    k_ws     <<<dim3(16, NH), 128>>>(kw);
    k_scores <<<dim3(16, 8, BS), 128>>>(x);
    k_softmax<<<dim3(NH, BS), 256>>>(mask);
    k_xw     <<<dim3(16, 4, BS), 256>>>(x);
    k_xwred  <<<512, 256>>>();
    k_ctx    <<<DIM, 256>>>(vw, vb);
    k_out    <<<DIM, 256>>>(ow, ob);
    k_ln     <<<1024, 256>>>(x, lg, lb, y);
}